// round 13
// baseline (speedup 1.0000x reference)
#include <cuda_runtime.h>
#include <math.h>

#define Sn 512
#define Bn 128
#define En 300
#define KP 304          // padded K for GEMM
#define Hn 256
#define Nc 2048         // combined gate width (fwd 1024 | bwd 1024)
#define Cn 6
#define Pn 256
#define H2 512
#define G3 1536
#define SAS 132         // A smem row stride (floats)
#define WDS 130         // W smem row stride (ull)

typedef unsigned long long ull;

// ---------------- f32x2 helpers ---------------------------------------------
__device__ __forceinline__ ull fma2(ull a, ull b, ull c) {
    ull d; asm("fma.rn.f32x2 %0, %1, %2, %3;" : "=l"(d) : "l"(a), "l"(b), "l"(c));
    return d;
}
__device__ __forceinline__ ull add2(ull a, ull b) {
    ull d; asm("add.rn.f32x2 %0, %1, %2;" : "=l"(d) : "l"(a), "l"(b));
    return d;
}
__device__ __forceinline__ ull pack2(float x, float y) {
    ull d; asm("mov.b64 %0, {%1, %2};" : "=l"(d) : "f"(x), "f"(y));
    return d;
}
__device__ __forceinline__ float2 unpack2(ull p) {
    float2 r; asm("mov.b64 {%0, %1}, %2;" : "=f"(r.x), "=f"(r.y) : "l"(p));
    return r;
}
__device__ __forceinline__ float sigf(float x) { return 1.f / (1.f + __expf(-x)); }
__device__ __forceinline__ float tanhfast(float x) {
    float e = __expf(2.f * x);
    return 1.f - __fdividef(2.f, e + 1.f);
}
__device__ __forceinline__ unsigned s2u(const void* p) {
    return (unsigned)__cvta_generic_to_shared(p);
}

// ---------------- scratch (static; no cudaMalloc) ---------------------------
__device__ float g_emb[Sn * Bn * KP];          // [S*B][304] zero-padded
__device__ float g_gx[(size_t)Sn * Bn * Nc];   // [S*B][2048] fwd|bwd gates
__device__ ull   g_Wd[Nc * KP];                // combined Wih, DUPLICATED pairs
__device__ float g_bc[Nc];                     // combined bih+bhh
__device__ float g_hbuf[2 * Bn * Hn];          // final h: [dir][b][h]
__device__ float g_hdec[2][Bn * H2];
__device__ float g_gxd[Cn * G3];
__device__ float g_dT[H2 * G3];
__device__ float g_pT[H2 * Pn];

// ---------------- embedding: g_emb[s*128+b][0:300] = tanh(embed_W[tok]) -----
__global__ void embed_kernel(const int* __restrict__ seq,
                             const float* __restrict__ embW) {
    int m = blockIdx.x;              // m = s*128 + b
    int s = m >> 7, b = m & 127;
    int tok = seq[b * Sn + s];
    const float* src = embW + (size_t)tok * En;
    float* dst = g_emb + (size_t)m * KP;
    for (int e = threadIdx.x; e < En; e += blockDim.x)
        dst[e] = tanhfast(src[e]);
    for (int e = En + threadIdx.x; e < KP; e += blockDim.x)
        dst[e] = 0.f;
}

// ---------------- build combined duplicated weights + bias ------------------
__global__ void prep_w(const float* __restrict__ fWih, const float* __restrict__ bWih,
                       const float* __restrict__ fbih, const float* __restrict__ fbhh,
                       const float* __restrict__ bbih, const float* __restrict__ bbhh) {
    int i = blockIdx.x * blockDim.x + threadIdx.x;
    if (i < Nc * KP) {
        int n = i / KP, e = i - n * KP;
        float v = 0.f;
        if (e < En) v = (n < 1024) ? fWih[n * En + e] : bWih[(n - 1024) * En + e];
        g_Wd[i] = pack2(v, v);
    }
    if (i < Nc)
        g_bc[i] = (i < 1024) ? (fbih[i] + fbhh[i]) : (bbih[i - 1024] + bbhh[i - 1024]);
}

// ---------------- f32x2 SGEMM v4: pre-duplicated W, no inner-loop packs -----
// BM=BN=128, BK=16, 256 threads, 8x8 per thread on m-pairs, double-buffered.
// W smem interleaved: ull slot for local n' = tx*8+o at [c*32 + tx*2 + e]
// (c=o>>1, e=o&1) so each LDS.128 reads 16B-contiguous per lane.
__global__ void __launch_bounds__(256, 2)
sgemm4(const float* __restrict__ A, const ull* __restrict__ Wd,
       const float* __restrict__ bias, float* __restrict__ C) {
    extern __shared__ ull dyns[];
    ull* Ws = dyns;                          // [2][16][WDS]
    float* As = (float*)(dyns + 2 * 16 * WDS);  // [2][16][SAS]
    int bm = blockIdx.y * 128, bn = blockIdx.x * 128;
    int t = threadIdx.x;
    int tx = t & 15, ty = t >> 4;
    int row = t >> 1;                 // 0..127
    int kc = (t & 1) * 8;             // 0 or 8
    // interleaved position for this thread's W row
    int wpos = ((row & 7) >> 1) * 32 + (row >> 3) * 2 + (row & 1);
    const float* Ap = A + (size_t)(bm + row) * KP + kc;
    const ull*   Wp = Wd + (size_t)(bn + row) * KP + kc;

    ull acc[4][8];
#pragma unroll
    for (int i = 0; i < 4; i++)
#pragma unroll
        for (int j = 0; j < 8; j++) acc[i][j] = 0ull;

    float4 a0 = *(const float4*)(Ap);
    float4 a1 = *(const float4*)(Ap + 4);
    ulonglong2 w0 = *(const ulonglong2*)(Wp);
    ulonglong2 w1 = *(const ulonglong2*)(Wp + 2);
    ulonglong2 w2 = *(const ulonglong2*)(Wp + 4);
    ulonglong2 w3 = *(const ulonglong2*)(Wp + 6);
    {
        float* as = As; ull* ws = Ws;
        as[(kc + 0) * SAS + row] = a0.x; as[(kc + 1) * SAS + row] = a0.y;
        as[(kc + 2) * SAS + row] = a0.z; as[(kc + 3) * SAS + row] = a0.w;
        as[(kc + 4) * SAS + row] = a1.x; as[(kc + 5) * SAS + row] = a1.y;
        as[(kc + 6) * SAS + row] = a1.z; as[(kc + 7) * SAS + row] = a1.w;
        ws[(kc + 0) * WDS + wpos] = w0.x; ws[(kc + 1) * WDS + wpos] = w0.y;
        ws[(kc + 2) * WDS + wpos] = w1.x; ws[(kc + 3) * WDS + wpos] = w1.y;
        ws[(kc + 4) * WDS + wpos] = w2.x; ws[(kc + 5) * WDS + wpos] = w2.y;
        ws[(kc + 6) * WDS + wpos] = w3.x; ws[(kc + 7) * WDS + wpos] = w3.y;
    }
    __syncthreads();

#pragma unroll 1
    for (int it = 0; it < 19; it++) {
        int buf = it & 1;
        if (it < 18) {
            int k0 = (it + 1) * 16;
            a0 = *(const float4*)(Ap + k0);
            a1 = *(const float4*)(Ap + k0 + 4);
            w0 = *(const ulonglong2*)(Wp + k0);
            w1 = *(const ulonglong2*)(Wp + k0 + 2);
            w2 = *(const ulonglong2*)(Wp + k0 + 4);
            w3 = *(const ulonglong2*)(Wp + k0 + 6);
        }
        const ull* ws = Ws + buf * 16 * WDS;
        const float* as = As + buf * 16 * SAS;
#pragma unroll 4
        for (int kk = 0; kk < 16; kk++) {
            const ull* ap = (const ull*)(as + kk * SAS + ty * 8);
            ull am[4] = {ap[0], ap[1], ap[2], ap[3]};
            const ull* wb = ws + kk * WDS + tx * 2;
            ulonglong2 c0 = *(const ulonglong2*)(wb);
            ulonglong2 c1 = *(const ulonglong2*)(wb + 32);
            ulonglong2 c2 = *(const ulonglong2*)(wb + 64);
            ulonglong2 c3 = *(const ulonglong2*)(wb + 96);
            ull wv[8] = {c0.x, c0.y, c1.x, c1.y, c2.x, c2.y, c3.x, c3.y};
#pragma unroll
            for (int mp = 0; mp < 4; mp++)
#pragma unroll
                for (int n = 0; n < 8; n++)
                    acc[mp][n] = fma2(am[mp], wv[n], acc[mp][n]);
        }
        if (it < 18) {
            float* as2 = As + (1 - buf) * 16 * SAS;
            ull* ws2 = Ws + (1 - buf) * 16 * WDS;
            as2[(kc + 0) * SAS + row] = a0.x; as2[(kc + 1) * SAS + row] = a0.y;
            as2[(kc + 2) * SAS + row] = a0.z; as2[(kc + 3) * SAS + row] = a0.w;
            as2[(kc + 4) * SAS + row] = a1.x; as2[(kc + 5) * SAS + row] = a1.y;
            as2[(kc + 6) * SAS + row] = a1.z; as2[(kc + 7) * SAS + row] = a1.w;
            ws2[(kc + 0) * WDS + wpos] = w0.x; ws2[(kc + 1) * WDS + wpos] = w0.y;
            ws2[(kc + 2) * WDS + wpos] = w1.x; ws2[(kc + 3) * WDS + wpos] = w1.y;
            ws2[(kc + 4) * WDS + wpos] = w2.x; ws2[(kc + 5) * WDS + wpos] = w2.y;
            ws2[(kc + 6) * WDS + wpos] = w3.x; ws2[(kc + 7) * WDS + wpos] = w3.y;
            __syncthreads();
        }
    }

    float4 bb0 = *(const float4*)(bias + bn + tx * 8);
    float4 bb1 = *(const float4*)(bias + bn + tx * 8 + 4);
#pragma unroll
    for (int mp = 0; mp < 4; mp++) {
        float2 h[8];
#pragma unroll
        for (int n = 0; n < 8; n++) h[n] = unpack2(acc[mp][n]);
        size_t m0 = (size_t)(bm + ty * 8 + mp * 2);
        float4 o;
        o.x = h[0].x + bb0.x; o.y = h[1].x + bb0.y; o.z = h[2].x + bb0.z; o.w = h[3].x + bb0.w;
        *(float4*)(C + m0 * Nc + bn + tx * 8) = o;
        o.x = h[4].x + bb1.x; o.y = h[5].x + bb1.y; o.z = h[6].x + bb1.z; o.w = h[7].x + bb1.w;
        *(float4*)(C + m0 * Nc + bn + tx * 8 + 4) = o;
        o.x = h[0].y + bb0.x; o.y = h[1].y + bb0.y; o.z = h[2].y + bb0.z; o.w = h[3].y + bb0.w;
        *(float4*)(C + (m0 + 1) * Nc + bn + tx * 8) = o;
        o.x = h[4].y + bb1.x; o.y = h[5].y + bb1.y; o.z = h[6].y + bb1.z; o.w = h[7].y + bb1.w;
        *(float4*)(C + (m0 + 1) * Nc + bn + tx * 8 + 4) = o;
    }
}
#define SGEMM4_SMEM (2 * 16 * WDS * 8 + 2 * 16 * SAS * 4)   // 33280+16896=50176

// ---------------- persistent BiLSTM: R8 compute + cluster DSMEM exchange ----
// 128 CTAs in 16 clusters of 8 (cluster = {dir,bg}; rank = uslot).
// Warps partition K (each weight read by ONE warp); cross-warp smem reduce.
// h exchange: each thread stores its (hx,hy) pair into all 8 peers'
// double-buffered hsm[phase][bp][k] via st.shared::cluster + barrier.cluster.
__global__ void __launch_bounds__(256, 1) __cluster_dims__(8, 1, 1)
lstm2c(const float* __restrict__ fWhh, const float* __restrict__ bWhh) {
    extern __shared__ float sm[];
    float* Wsm = sm;                       // [256 k][129 pad]
    ull* red = (ull*)(sm + 256 * 129);     // [8 w][4 g][8 bp][32 u]
    ull* hsm = red + 8192;                 // [2 phase][8 bp][256 k]

    int bx = blockIdx.x;
    int dir = bx >> 6;
    int L = bx & 63;
    int bg = L >> 3, uslot = L & 7;
    int u0 = uslot * 32, b0 = bg * 16;
    const float* Whh = dir ? bWhh : fWhh;
    const float* gx = g_gx + dir * 1024;
    int t = threadIdx.x, w = t >> 5, u = t & 31;

    // load Whh slice: Wsm[k*129 + g*32+uu] = Whh[(g*256+u0+uu)*256 + k]
    for (int i = t; i < 32768; i += 256) {
        int k = i & 255, r = i >> 8;
        int g = r >> 5, uu = r & 31;
        Wsm[k * 129 + r] = Whh[(size_t)(g * Hn + u0 + uu) * Hn + k];
    }
    // zero phase-0 h
    for (int i = t; i < 2048; i += 256) hsm[i] = 0ull;
    __syncthreads();
    asm volatile("barrier.cluster.arrive.aligned;" ::: "memory");
    asm volatile("barrier.cluster.wait.aligned;" ::: "memory");

    // per-thread write slot (phase 0): hsm[0][bp=w][k=u0+u]
    unsigned haddr0 = s2u(hsm) + (unsigned)((w * 256 + u0 + u) * 8);
    float2 cc = make_float2(0.f, 0.f);

    for (int s = 0; s < Sn; s++) {
        int p = s & 1;
        // prefetch gx for this thread's outputs (consumed at reduce)
        int xs = dir ? ((Sn - s) & (Sn - 1)) : s;
        const float* gp = gx + ((size_t)(xs * Bn + b0 + 2 * w)) * Nc + u0 + u;
        float ga0[4], ga1[4];
#pragma unroll
        for (int g = 0; g < 4; g++) {
            ga0[g] = gp[g * Hn];
            ga1[g] = gp[Nc + g * Hn];
        }

        // partial gate dots over this warp's k slice
        const ull* hb = hsm + p * 2048;
        ull acc[4][8];
#pragma unroll
        for (int g = 0; g < 4; g++)
#pragma unroll
            for (int bp = 0; bp < 8; bp++) acc[g][bp] = 0ull;
#pragma unroll 4
        for (int kk = 0; kk < 32; kk++) {
            int k = w * 32 + kk;
            ull hv[8];
#pragma unroll
            for (int bp = 0; bp < 8; bp++) hv[bp] = hb[bp * 256 + k];
            const float* wr = Wsm + k * 129 + u;
            ull W0 = pack2(wr[0], wr[0]);
            ull W1 = pack2(wr[32], wr[32]);
            ull W2 = pack2(wr[64], wr[64]);
            ull W3 = pack2(wr[96], wr[96]);
#pragma unroll
            for (int bp = 0; bp < 8; bp++) {
                acc[0][bp] = fma2(W0, hv[bp], acc[0][bp]);
                acc[1][bp] = fma2(W1, hv[bp], acc[1][bp]);
                acc[2][bp] = fma2(W2, hv[bp], acc[2][bp]);
                acc[3][bp] = fma2(W3, hv[bp], acc[3][bp]);
            }
        }
        // stash partials
#pragma unroll
        for (int g = 0; g < 4; g++)
#pragma unroll
            for (int bp = 0; bp < 8; bp++)
                red[((w * 4 + g) * 8 + bp) * 32 + u] = acc[g][bp];
        __syncthreads();

        // reduce across warps; thread owns (bp=w, u)
        ull s0 = pack2(ga0[0], ga1[0]);
        ull s1 = pack2(ga0[1], ga1[1]);
        ull s2 = pack2(ga0[2], ga1[2]);
        ull s3 = pack2(ga0[3], ga1[3]);
#pragma unroll
        for (int ww = 0; ww < 8; ww++) {
            const ull* rp = red + ((ww * 4) * 8 + w) * 32 + u;
            s0 = add2(s0, rp[0]);
            s1 = add2(s1, rp[8 * 32]);
            s2 = add2(s2, rp[16 * 32]);
            s3 = add2(s3, rp[24 * 32]);
        }
        float2 iv = unpack2(s0), fv = unpack2(s1), gv = unpack2(s2), ov = unpack2(s3);
        cc.x = sigf(fv.x) * cc.x + sigf(iv.x) * tanhfast(gv.x);
        cc.y = sigf(fv.y) * cc.y + sigf(iv.y) * tanhfast(gv.y);
        float hx = sigf(ov.x) * tanhfast(cc.x);
        float hy = sigf(ov.y) * tanhfast(cc.y);

        if (s < Sn - 1) {
            // broadcast pair into every cluster CTA's next-phase hsm
            ull hp2 = pack2(hx, hy);
            unsigned dst = haddr0 + (unsigned)((1 - p) * 16384);
#pragma unroll
            for (int r = 0; r < 8; r++) {
                asm volatile(
                    "{\n\t.reg .b32 ra;\n\t"
                    "mapa.shared::cluster.u32 ra, %0, %1;\n\t"
                    "st.shared::cluster.u64 [ra], %2;\n\t}"
                    :: "r"(dst), "r"(r), "l"(hp2) : "memory");
            }
            asm volatile("barrier.cluster.arrive.aligned;" ::: "memory");
            asm volatile("barrier.cluster.wait.aligned;" ::: "memory");
        } else {
            float* hb2 = g_hbuf + (size_t)dir * Bn * Hn;
            hb2[(b0 + 2 * w) * Hn + u0 + u] = hx;
            hb2[(b0 + 2 * w + 1) * Hn + u0 + u] = hy;
        }
    }
}
#define LSTM2C_SMEM (256 * 129 * 4 + 8192 * 8 + 2 * 8 * 256 * 8)  // 230400 B

// ---------------- pack final fh|bh into decoder h0 --------------------------
__global__ void pack_h0() {
    int i = blockIdx.x * blockDim.x + threadIdx.x;
    if (i >= Bn * H2) return;
    int b = i >> 9, j = i & 511;
    g_hdec[0][i] = g_hbuf[(size_t)(j >> 8) * Bn * Hn + b * Hn + (j & 255)];
}

// ---------------- generic transpose -----------------------------------------
__global__ void transpose_kernel(const float* __restrict__ in,
                                 float* __restrict__ out, int J, int K) {
    int i = blockIdx.x * blockDim.x + threadIdx.x;
    if (i >= J * K) return;
    int j = i / K, k = i - j * K;
    out[k * J + j] = in[i];
}

// ---------------- decoder input gates ---------------------------------------
__global__ void gxd_kernel(const int* __restrict__ classes,
                           const float* __restrict__ ecW,
                           const float* __restrict__ dWih,
                           const float* __restrict__ dbih) {
    __shared__ float ce[En];
    int c = blockIdx.x;
    int cidx = classes[c];
    for (int e = threadIdx.x; e < En; e += blockDim.x)
        ce[e] = tanhfast(ecW[(size_t)cidx * En + e]);
    __syncthreads();
    for (int j = threadIdx.x; j < G3; j += blockDim.x) {
        float acc = dbih[j];
        const float* w = dWih + (size_t)j * En;
        for (int e = 0; e < En; e++) acc += ce[e] * w[e];
        g_gxd[c * G3 + j] = acc;
    }
}

// ---------------- GRU decoder step ------------------------------------------
__global__ void dec_step1(int c, int srcp, const float* __restrict__ dbhh) {
    __shared__ float hsm[16 * H2];
    const float* src = g_hdec[srcp];
    float* dst = g_hdec[1 - srcp];
    int b0 = blockIdx.y * 16;
    int u0 = blockIdx.x * 32;
    int t = threadIdx.x;
    for (int i = t; i < 16 * H2; i += 256)
        hsm[i] = src[(b0 + (i >> 9)) * H2 + (i & 511)];
    __syncthreads();

    int u = u0 + (t & 31);
    int bp = t >> 5;
    const float* h0p = hsm + (bp * 2) * H2;
    const float* h1p = hsm + (bp * 2 + 1) * H2;
    float r0 = 0, z0 = 0, n0 = 0, r1 = 0, z1 = 0, n1 = 0;
    const float* w = g_dT + u;
#pragma unroll 4
    for (int k = 0; k < H2; k++) {
        float wr = w[(size_t)k * G3];
        float wz = w[(size_t)k * G3 + 512];
        float wn = w[(size_t)k * G3 + 1024];
        float x0 = h0p[k], x1 = h1p[k];
        r0 += x0 * wr; z0 += x0 * wz; n0 += x0 * wn;
        r1 += x1 * wr; z1 += x1 * wz; n1 += x1 * wn;
    }
    float br = dbhh[u], bz = dbhh[512 + u], bn = dbhh[1024 + u];
    float gr = g_gxd[c * G3 + u];
    float gz = g_gxd[c * G3 + 512 + u];
    float gn = g_gxd[c * G3 + 1024 + u];

    float R0 = sigf(gr + r0 + br);
    float Z0 = sigf(gz + z0 + bz);
    float N0 = tanhfast(gn + R0 * (n0 + bn));
    dst[(b0 + bp * 2) * H2 + u] = tanhfast((1.f - Z0) * N0 + Z0 * h0p[u]);

    float R1 = sigf(gr + r1 + br);
    float Z1 = sigf(gz + z1 + bz);
    float N1 = tanhfast(gn + R1 * (n1 + bn));
    dst[(b0 + bp * 2 + 1) * H2 + u] = tanhfast((1.f - Z1) * N1 + Z1 * h1p[u]);
}

// ---------------- proj + cls + log_softmax ----------------------------------
__global__ void dec_step2(int c, int hp, const float* __restrict__ projb,
                          const float* __restrict__ clsW,
                          const float* __restrict__ clsb,
                          float* __restrict__ out) {
    __shared__ float hsm[H2];
    __shared__ float r0s[256], r1s[256];
    int b = blockIdx.x;
    const float* h = g_hdec[hp] + (size_t)b * H2;
    int t = threadIdx.x;
    hsm[t] = h[t];
    hsm[t + 256] = h[t + 256];
    __syncthreads();
    float p = projb[t];
    const float* w = g_pT + t;
#pragma unroll 4
    for (int k = 0; k < H2; k++) p += hsm[k] * w[(size_t)k * Pn];
    r0s[t] = p * clsW[t];
    r1s[t] = p * clsW[256 + t];
    __syncthreads();
    for (int off = 128; off > 0; off >>= 1) {
        if (t < off) {
            r0s[t] += r0s[t + off];
            r1s[t] += r1s[t + off];
        }
        __syncthreads();
    }
    if (t == 0) {
        float l0 = r0s[0] + clsb[0], l1 = r1s[0] + clsb[1];
        float m = fmaxf(l0, l1);
        float lse = m + logf(expf(l0 - m) + expf(l1 - m));
        out[(c * Bn + b) * 2 + 0] = l0 - lse;
        out[(c * Bn + b) * 2 + 1] = l1 - lse;
    }
}

// ---------------- launch ----------------------------------------------------
extern "C" void kernel_launch(void* const* d_in, const int* in_sizes, int n_in,
                              void* d_out, int out_size) {
    const int*   seq     = (const int*)d_in[0];
    const int*   classes = (const int*)d_in[1];
    const float* embW    = (const float*)d_in[2];
    const float* ecW     = (const float*)d_in[3];
    const float* fWih    = (const float*)d_in[4];
    const float* fWhh    = (const float*)d_in[5];
    const float* fbih    = (const float*)d_in[6];
    const float* fbhh    = (const float*)d_in[7];
    const float* bWih    = (const float*)d_in[8];
    const float* bWhh    = (const float*)d_in[9];
    const float* bbih    = (const float*)d_in[10];
    const float* bbhh    = (const float*)d_in[11];
    const float* dWih    = (const float*)d_in[12];
    const float* dWhh    = (const float*)d_in[13];
    const float* dbih    = (const float*)d_in[14];
    const float* dbhh    = (const float*)d_in[15];
    const float* projW   = (const float*)d_in[16];
    const float* projb   = (const float*)d_in[17];
    const float* clsW    = (const float*)d_in[18];
    const float* clsb    = (const float*)d_in[19];
    float* out = (float*)d_out;

    cudaFuncSetAttribute(lstm2c, cudaFuncAttributeMaxDynamicSharedMemorySize,
                         LSTM2C_SMEM);
    cudaFuncSetAttribute(sgemm4, cudaFuncAttributeMaxDynamicSharedMemorySize,
                         SGEMM4_SMEM);

    float *emb_p, *gx_p, *bc_p, *dT_p, *pT_p;
    ull* Wd_p;
    cudaGetSymbolAddress((void**)&emb_p, g_emb);
    cudaGetSymbolAddress((void**)&gx_p, g_gx);
    cudaGetSymbolAddress((void**)&Wd_p, g_Wd);
    cudaGetSymbolAddress((void**)&bc_p, g_bc);
    cudaGetSymbolAddress((void**)&dT_p, g_dT);
    cudaGetSymbolAddress((void**)&pT_p, g_pT);

    embed_kernel<<<Sn * Bn, 128>>>(seq, embW);
    prep_w<<<(Nc * KP + 255) / 256, 256>>>(fWih, bWih, fbih, fbhh, bbih, bbhh);

    dim3 ggrid(Nc / 128, (Sn * Bn) / 128);
    sgemm4<<<ggrid, 256, SGEMM4_SMEM>>>(emb_p, Wd_p, bc_p, gx_p);

    transpose_kernel<<<(G3 * H2 + 255) / 256, 256>>>(dWhh, dT_p, G3, H2);
    transpose_kernel<<<(Pn * H2 + 255) / 256, 256>>>(projW, pT_p, Pn, H2);
    gxd_kernel<<<Cn, 256>>>(classes, ecW, dWih, dbih);

    lstm2c<<<128, 256, LSTM2C_SMEM>>>(fWhh, bWhh);
    pack_h0<<<(Bn * H2 + 255) / 256, 256>>>();

    for (int c = 0; c < Cn; c++) {
        int sp = c & 1;
        dim3 dgrid(16, 8);
        dec_step1<<<dgrid, 256>>>(c, sp, dbhh);
        dec_step2<<<Bn, 256>>>(c, 1 - sp, projb, clsW, clsb, out);
    }
}